// round 14
// baseline (speedup 1.0000x reference)
#include <cuda_runtime.h>

// EMA y_t = (1-w)*y_{t-1} + w*x_t — run-granular two-pass lookback scan, v9.
// Little's-law fix: pass 1 is CONTINUOUS MLP-16 streaming reads (computes the
// run aggregate, primes L2); after one run-level lookback, pass 2 re-reads the
// run from L2 and streams outputs. Concurrency capped at 4 CTAs/SM so the
// in-flight pass1->pass2 working set (592 x 128KB = 74MB) fits in 126MB L2
// (v4's failure mode, fixed by sizing). No register stash -> ~36 regs.
// Run = 128 timesteps; carries are run-granular (2MB, near-free clear).

#define TT    8192
#define CC    256
#define RUN   128
#define NRUNS (TT / RUN)   // 64 runs per batch row
#define MAXB  16

// packed carry per (b,run,channel): high 32 = flag (0 none/1 agg/2 prefix),
// low 32 = float payload. Zeroed each launch.
__device__ unsigned long long g_carry[MAXB * NRUNS * CC];

__global__ void ema_clear_kernel(int n2) {
    int i = blockIdx.x * blockDim.x + threadIdx.x;
    if (i < n2) ((ulonglong2*)g_carry)[i] = make_ulonglong2(0ULL, 0ULL);
}

__global__ __launch_bounds__(CC, 4) void ema_scan_kernel(
    const float* __restrict__ x,
    const float* __restrict__ y0,
    const float* __restrict__ smooth,
    float* __restrict__ out,
    int B)
{
    // batch-fast: predecessor run (r-1,b) is exactly B bids lower.
    const int b = blockIdx.x % B;
    const int r = blockIdx.x / B;
    const int c = threadIdx.x;

    const float w = fminf(fmaxf(smooth[c], 0.0f), 1.0f);
    const float a = 1.0f - w;

    // ---- Pass 1: continuous MLP-16 read of the run (prime L2), computing
    //      the zero-entry run aggregate e = sum a^(RUN-1-i) w x_i. ----
    const float* xp = x + ((size_t)(b * TT + r * RUN) * CC + c);
    float e = 0.0f;
#pragma unroll
    for (int g16 = 0; g16 < RUN / 16; g16++) {
        float v[16];
#pragma unroll
        for (int i = 0; i < 16; i++) v[i] = __ldcg(xp + (g16 * 16 + i) * CC);
#pragma unroll
        for (int i = 0; i < 16; i++) e = fmaf(a, e, w * v[i]);
    }

    // AL = a^128 via 7 squarings
    float t = a * a;        // a^2
    t *= t;                 // a^4
    t *= t;                 // a^8
    t *= t;                 // a^16
    t *= t;                 // a^32
    t *= t;                 // a^64
    const float AL = t * t; // a^128

    volatile unsigned long long* cb = g_carry + (size_t)(b * NRUNS) * CC;

    // publish run aggregate (flag=1): aligned 8B store = atomic, no fence
    cb[(size_t)r * CC + c] =
        (1ULL << 32) | (unsigned long long)__float_as_uint(e);

    // ---- Run-level lookback: fold predecessor aggregates, short-circuit
    //      on inclusive prefixes. ----
    float acc;
    if (r == 0) {
        acc = y0[b * CC + c];
    } else {
        acc = 0.0f;
        float m = 1.0f;
        int j = r - 1;
        bool done = false;
        while (!done) {
            const int g = (j + 1 < 8) ? (j + 1) : 8;
            unsigned long long v[8];
            bool allset;
            do {  // batched spin: 8 independent volatile 8B reads per round
                allset = true;
#pragma unroll
                for (int u = 0; u < 8; u++) {
                    if (u < g) {
                        v[u] = cb[(size_t)(j - u) * CC + c];
                        if ((unsigned)(v[u] >> 32) == 0u) allset = false;
                    }
                }
            } while (!allset);
#pragma unroll
            for (int u = 0; u < 8; u++) {
                if (u < g) {
                    const unsigned f = (unsigned)(v[u] >> 32);
                    const float val = __uint_as_float((unsigned)(v[u] & 0xFFFFFFFFu));
                    acc = fmaf(m, val, acc);
                    if (f == 2u) { done = true; break; }  // inclusive prefix
                    m *= AL;                              // zero-start aggregate
                }
            }
            if (!done) {
                j -= g;
                if (j < 0) {  // all aggregates folded; add initial-state term
                    acc = fmaf(m, y0[b * CC + c], acc);
                    done = true;
                }
            }
        }
    }

    // publish inclusive run prefix (flag=2) for downstream short-circuit
    const float P = fmaf(AL, acc, e);
    cb[(size_t)r * CC + c] =
        (2ULL << 32) | (unsigned long long)__float_as_uint(P);

    // ---- Pass 2: re-read the run (L2-resident; __ldcs = evict after last
    //      use), run the recurrence from the known entry state, stream out. ----
    float* op = out + ((size_t)(b * TT + r * RUN) * CC + c);
    float y = acc;
#pragma unroll
    for (int g8 = 0; g8 < RUN / 8; g8++) {
        float v[8];
#pragma unroll
        for (int i = 0; i < 8; i++) v[i] = __ldcs(xp + (g8 * 8 + i) * CC);
#pragma unroll
        for (int i = 0; i < 8; i++) {
            y = fmaf(a, y, w * v[i]);
            __stcs(op + (g8 * 8 + i) * CC, y);
        }
    }
}

extern "C" void kernel_launch(void* const* d_in, const int* in_sizes, int n_in,
                              void* d_out, int out_size) {
    const float* x      = (const float*)d_in[0];  // [B, T, C]
    const float* y0     = (const float*)d_in[1];  // [B, C]
    const float* smooth = (const float*)d_in[2];  // [C]
    float* out          = (float*)d_out;

    const int B = in_sizes[0] / (TT * CC);

    const int n2 = (B * NRUNS * CC) / 2;          // ulonglong2 words
    ema_clear_kernel<<<(n2 + 255) / 256, 256>>>(n2);
    ema_scan_kernel<<<B * NRUNS, CC>>>(x, y0, smooth, out, B);
}